// round 15
// baseline (speedup 1.0000x reference)
#include <cuda_runtime.h>
#include <math.h>

#define NN 100000
#define NE 800000
#define KDIM 128
#define H1 8
#define C1 16
#define D1 128
#define H2 10
#define C2 10
#define D2 100
#define NEG_SLOPE 0.2f

// ---------------- scratch (device globals: no allocation allowed) ----------
__device__ float g_h1[NN * D1];      // x @ W1
__device__ float g_hact[NN * D1];    // elu(emb1)
__device__ float g_h2[NN * D2];      // hact @ W2
__device__ float g_as1[NN * H1];
__device__ float g_ad1[NN * H1];
__device__ float g_as2[NN * H2];
__device__ float g_ad2[NN * H2];
__device__ int   g_deg[NN];
__device__ int   g_off[NN + 1];
__device__ int   g_cur[NN];
__device__ int   g_src[NE];          // CSR-by-dst: source node per slot
__device__ float g_loss_num;
__device__ float g_loss_cnt;

// ---------------- CSR build ------------------------------------------------
__global__ void init_kernel() {
    int i = blockIdx.x * blockDim.x + threadIdx.x;
    if (i < NN) g_deg[i] = 0;
    if (i == 0) { g_loss_num = 0.f; g_loss_cnt = 0.f; }
}

__global__ void count_kernel(const int* __restrict__ ei) {
    int e = blockIdx.x * blockDim.x + threadIdx.x;
    if (e >= NE) return;
    int d = __ldg(&ei[NE + e]);
    if ((unsigned)d < NN) atomicAdd(&g_deg[d], 1);
}

__global__ void scan_kernel() {
    __shared__ int sh[1024];
    int t = threadIdx.x;
    const int CH = (NN + 1023) / 1024;   // 98
    int start = t * CH;
    int s = 0;
    for (int i = 0; i < CH; i++) {
        int idx = start + i;
        if (idx < NN) s += g_deg[idx];
    }
    sh[t] = s;
    __syncthreads();
    for (int d = 1; d < 1024; d <<= 1) {
        int v = (t >= d) ? sh[t - d] : 0;
        __syncthreads();
        sh[t] += v;
        __syncthreads();
    }
    int run = (t == 0) ? 0 : sh[t - 1];
    for (int i = 0; i < CH; i++) {
        int idx = start + i;
        if (idx < NN) { g_off[idx] = run; g_cur[idx] = run; run += g_deg[idx]; }
    }
    if (t == 1023) g_off[NN] = sh[1023];
}

__global__ void scatter_kernel(const int* __restrict__ ei) {
    int e = blockIdx.x * blockDim.x + threadIdx.x;
    if (e >= NE) return;
    int d = __ldg(&ei[NE + e]);
    int srcv = __ldg(&ei[e]);
    if ((unsigned)d >= NN || (unsigned)srcv >= NN) return;
    int pos = atomicAdd(&g_cur[d], 1);
    g_src[pos] = srcv;
}

// ---------------- SGEMM: Y[N, M] = X[N, 128] @ W[128, M] -------------------
// 256 threads/block, 64 rows/block (proven R13 build: 733.5 us).
template <int M>
__device__ __forceinline__ void gemm_body(const float* __restrict__ X,
                                          const float* __restrict__ W,
                                          float* __restrict__ Y) {
    const int KC = 32;
    __shared__ float Wt[M][KC + 4];    // stride 36
    __shared__ float Xs[64][KC];       // warp-uniform broadcast reads
    int t   = threadIdx.x;
    int col = t & 127;
    int rh  = t >> 7;                  // 0 or 1; uniform within a warp
    int rbase = rh * 32;
    int row0 = blockIdx.x * 64;
    float acc[32];
#pragma unroll
    for (int r = 0; r < 32; r++) acc[r] = 0.f;

    for (int kc = 0; kc < KDIM; kc += KC) {
        for (int idx = t; idx < M * KC; idx += 256) {
            int m = idx % M, k = idx / M;           // coalesced over m
            Wt[m][k] = W[(size_t)(kc + k) * M + m];
        }
        for (int idx = t; idx < 64 * KC; idx += 256) {
            int r = idx / KC, k = idx % KC;
            int row = row0 + r;
            Xs[r][k] = (row < NN) ? X[(size_t)row * KDIM + kc + k] : 0.f;
        }
        __syncthreads();
        if (col < M) {
#pragma unroll
            for (int kk = 0; kk < KC; kk += 4) {
                float4 w = *(const float4*)&Wt[col][kk];
#pragma unroll
                for (int r = 0; r < 32; r++) {
                    float4 xv = *(const float4*)&Xs[rbase + r][kk];
                    acc[r] = fmaf(w.x, xv.x, acc[r]);
                    acc[r] = fmaf(w.y, xv.y, acc[r]);
                    acc[r] = fmaf(w.z, xv.z, acc[r]);
                    acc[r] = fmaf(w.w, xv.w, acc[r]);
                }
            }
        }
        __syncthreads();
    }
    if (col < M) {
#pragma unroll
        for (int r = 0; r < 32; r++) {
            int row = row0 + rbase + r;
            if (row < NN) Y[(size_t)row * M + col] = acc[r];
        }
    }
}

__global__ void __launch_bounds__(256) gemm1_kernel(const float* __restrict__ X,
                                                    const float* __restrict__ W) {
    gemm_body<D1>(X, W, g_h1);
}
__global__ void __launch_bounds__(256) gemm2_kernel(const float* __restrict__ W) {
    gemm_body<D2>(g_hact, W, g_h2);
}

// ---------------- attention coefficients as/ad -----------------------------
template <int H, int C>
__device__ __forceinline__ void alpha_body(const float* __restrict__ Hm,
                                           const float* __restrict__ asr,
                                           const float* __restrict__ adt,
                                           float* __restrict__ o_as,
                                           float* __restrict__ o_ad) {
    int idx = blockIdx.x * blockDim.x + threadIdx.x;   // n*H + h
    if (idx >= NN * H) return;
    int n = idx / H, h = idx % H;
    const float* hp = Hm + (size_t)n * (H * C) + h * C;
    float s = 0.f, d = 0.f;
#pragma unroll
    for (int c = 0; c < C; c++) {
        float v = hp[c];
        s = fmaf(v, asr[h * C + c], s);
        d = fmaf(v, adt[h * C + c], d);
    }
    o_as[idx] = s;
    o_ad[idx] = d;
}

__global__ void alpha1_kernel(const float* __restrict__ asr, const float* __restrict__ adt) {
    alpha_body<H1, C1>(g_h1, asr, adt, g_as1, g_ad1);
}
__global__ void alpha2_kernel(const float* __restrict__ asr, const float* __restrict__ adt) {
    alpha_body<H2, C2>(g_h2, asr, adt, g_as2, g_ad2);
}

// ---------------- layer 1: single-pass flash softmax+agg, 2-way unrolled ---
// 1 warp/node; lane covers channels lane*4..+3 (head = lane/4).
// Even/odd edges use independent online-softmax states (halves the serial
// exp/max chain, doubles load MLP); merged at the end with the flash identity.
__global__ void agg1_kernel(float* __restrict__ emb1, const float* __restrict__ b1) {
    int warp = (blockIdx.x * blockDim.x + threadIdx.x) >> 5;
    int lane = threadIdx.x & 31;
    if (warp >= NN) return;
    int n = warp;
    int beg = g_off[n], end = g_off[n + 1];
    int h  = lane >> 2;
    int c0 = lane * 4;
    float adh = __ldg(&g_ad1[n * H1 + h]);

    float mA = -3.0e38f, sA = 0.f;
    float a0 = 0.f, a1 = 0.f, a2 = 0.f, a3 = 0.f;
    float mB = -3.0e38f, sB = 0.f;
    float b0 = 0.f, b1r = 0.f, b2r = 0.f, b3 = 0.f;

    int e = beg;
    for (; e + 1 < end; e += 2) {
        int srcA = __ldg(&g_src[e]);
        int srcB = __ldg(&g_src[e + 1]);
        float lA = __ldg(&g_as1[srcA * H1 + h]) + adh;
        float lB = __ldg(&g_as1[srcB * H1 + h]) + adh;
        float4 hvA = __ldg((const float4*)&g_h1[(size_t)srcA * D1 + c0]);
        float4 hvB = __ldg((const float4*)&g_h1[(size_t)srcB * D1 + c0]);
        lA = lA > 0.f ? lA : NEG_SLOPE * lA;
        lB = lB > 0.f ? lB : NEG_SLOPE * lB;
        float mnA = fmaxf(mA, lA);
        float mnB = fmaxf(mB, lB);
        float scA = __expf(mA - mnA), pA = __expf(lA - mnA);
        float scB = __expf(mB - mnB), pB = __expf(lB - mnB);
        mA = mnA; mB = mnB;
        sA = fmaf(sA, scA, pA);
        sB = fmaf(sB, scB, pB);
        a0 = fmaf(a0, scA, pA * hvA.x);
        a1 = fmaf(a1, scA, pA * hvA.y);
        a2 = fmaf(a2, scA, pA * hvA.z);
        a3 = fmaf(a3, scA, pA * hvA.w);
        b0 = fmaf(b0, scB, pB * hvB.x);
        b1r = fmaf(b1r, scB, pB * hvB.y);
        b2r = fmaf(b2r, scB, pB * hvB.z);
        b3 = fmaf(b3, scB, pB * hvB.w);
    }
    if (e < end) {
        int src = __ldg(&g_src[e]);
        float l = __ldg(&g_as1[src * H1 + h]) + adh;
        float4 hv = __ldg((const float4*)&g_h1[(size_t)src * D1 + c0]);
        l = l > 0.f ? l : NEG_SLOPE * l;
        float mn = fmaxf(mA, l);
        float sc = __expf(mA - mn), p = __expf(l - mn);
        mA = mn;
        sA = fmaf(sA, sc, p);
        a0 = fmaf(a0, sc, p * hv.x);
        a1 = fmaf(a1, sc, p * hv.y);
        a2 = fmaf(a2, sc, p * hv.z);
        a3 = fmaf(a3, sc, p * hv.w);
    }
    // merge state B into A (exp(-huge)=0 cleanly kills unused states)
    {
        float mn = fmaxf(mA, mB);
        float scA = __expf(mA - mn);
        float scB = __expf(mB - mn);
        sA = sA * scA + sB * scB;
        a0 = a0 * scA + b0 * scB;
        a1 = a1 * scA + b1r * scB;
        a2 = a2 * scA + b2r * scB;
        a3 = a3 * scA + b3 * scB;
    }
    float inv = 1.f / (sA + 1e-16f);
    float v0 = a0 * inv + b1[c0 + 0];
    float v1 = a1 * inv + b1[c0 + 1];
    float v2 = a2 * inv + b1[c0 + 2];
    float v3 = a3 * inv + b1[c0 + 3];
    float* op = emb1 + (size_t)n * D1 + c0;
    op[0] = v0; op[1] = v1; op[2] = v2; op[3] = v3;
    float* hp = g_hact + (size_t)n * D1 + c0;
    hp[0] = v0 > 0.f ? v0 : expm1f(v0);
    hp[1] = v1 > 0.f ? v1 : expm1f(v1);
    hp[2] = v2 > 0.f ? v2 : expm1f(v2);
    hp[3] = v3 > 0.f ? v3 : expm1f(v3);
}

// ---------------- layer 2: softmax + aggregation + head-mean ---------------
__global__ void agg2_kernel(float* __restrict__ emb2, const float* __restrict__ b2) {
    __shared__ float sh[8][D2];
    int warp_l = threadIdx.x >> 5;
    int warp = (blockIdx.x * blockDim.x + threadIdx.x) >> 5;
    int lane = threadIdx.x & 31;
    if (warp >= NN) return;
    int n = warp;
    int beg = g_off[n], end = g_off[n + 1];

    int j = (lane < 30) ? (lane / 10) : 3;
    int h = (lane < 30) ? (lane % 10) : 0;
    float adh = __ldg(&g_ad2[n * H2 + h]);

    float m = -3.0e38f, s = 0.f;
    if (j < 3) {
        for (int e = beg + j; e < end; e += 3) {
            int src = __ldg(&g_src[e]);
            float l = __ldg(&g_as2[src * H2 + h]) + adh;
            l = l > 0.f ? l : NEG_SLOPE * l;
            float mn = fmaxf(m, l);
            s = s * __expf(m - mn) + __expf(l - mn);
            m = mn;
        }
    }
#pragma unroll
    for (int off = 10; off <= 20; off += 10) {
        float mo = __shfl_down_sync(0xffffffffu, m, off);
        float so = __shfl_down_sync(0xffffffffu, s, off);
        if (lane < 10) {
            float mn = fmaxf(m, mo);
            s = s * __expf(m - mn) + so * __expf(mo - mn);
            m = mn;
        }
    }
    float inv = 1.f / (s + 1e-16f);

    int cl = lane < 25 ? lane : 24;          // lanes 25..31 shadow lane 24 (writes guarded)
    int c0 = cl * 4;
    int hA = (c0 + 0) / C2, hB = (c0 + 1) / C2, hC = (c0 + 2) / C2, hD = (c0 + 3) / C2;
    float mA = __shfl_sync(0xffffffffu, m, hA),   iA = __shfl_sync(0xffffffffu, inv, hA);
    float mB = __shfl_sync(0xffffffffu, m, hB),   iB = __shfl_sync(0xffffffffu, inv, hB);
    float mC = __shfl_sync(0xffffffffu, m, hC),   iC = __shfl_sync(0xffffffffu, inv, hC);
    float mD = __shfl_sync(0xffffffffu, m, hD),   iD = __shfl_sync(0xffffffffu, inv, hD);
    float dA = __shfl_sync(0xffffffffu, adh, hA), dB = __shfl_sync(0xffffffffu, adh, hB);
    float dC = __shfl_sync(0xffffffffu, adh, hC), dD = __shfl_sync(0xffffffffu, adh, hD);

    float a0 = 0.f, a1 = 0.f, a2 = 0.f, a3 = 0.f;
    for (int e = beg; e < end; e++) {
        int src = __ldg(&g_src[e]);
        const float* hb = g_h2 + (size_t)src * D2;
        float4 hv = __ldg((const float4*)&hb[c0]);
        const float* ap = g_as2 + src * H2;
        float lA = __ldg(&ap[hA]) + dA; lA = lA > 0.f ? lA : NEG_SLOPE * lA;
        float lB = __ldg(&ap[hB]) + dB; lB = lB > 0.f ? lB : NEG_SLOPE * lB;
        float lC = __ldg(&ap[hC]) + dC; lC = lC > 0.f ? lC : NEG_SLOPE * lC;
        float lD = __ldg(&ap[hD]) + dD; lD = lD > 0.f ? lD : NEG_SLOPE * lD;
        a0 = fmaf(__expf(lA - mA) * iA, hv.x, a0);
        a1 = fmaf(__expf(lB - mB) * iB, hv.y, a1);
        a2 = fmaf(__expf(lC - mC) * iC, hv.z, a2);
        a3 = fmaf(__expf(lD - mD) * iD, hv.w, a3);
    }
    if (lane < 25) {
        sh[warp_l][c0 + 0] = a0;
        sh[warp_l][c0 + 1] = a1;
        sh[warp_l][c0 + 2] = a2;
        sh[warp_l][c0 + 3] = a3;
    }
    __syncwarp();
    if (lane < C2) {
        float acc = 0.f;
#pragma unroll
        for (int hh = 0; hh < H2; hh++) acc += sh[warp_l][hh * C2 + lane];
        emb2[(size_t)n * C2 + lane] = acc * (1.f / H2) + b2[lane];
    }
}

// ---------------- masked cross-entropy loss --------------------------------
__global__ void loss_kernel(const float* __restrict__ emb2,
                            const int* __restrict__ lab,
                            const unsigned char* __restrict__ mask) {
    int n = blockIdx.x * blockDim.x + threadIdx.x;
    float ce = 0.f, c = 0.f;
    if (n < NN && mask[n]) {
        const float* r = emb2 + (size_t)n * C2;
        float mx = r[0];
#pragma unroll
        for (int o = 1; o < C2; o++) mx = fmaxf(mx, r[o]);
        float se = 0.f;
#pragma unroll
        for (int o = 0; o < C2; o++) se += expf(r[o] - mx);
        float lse = mx + logf(se);
        int lb = lab[n];
        if ((unsigned)lb < C2) ce = lse - r[lb];
        c = 1.f;
    }
#pragma unroll
    for (int d = 16; d > 0; d >>= 1) {
        ce += __shfl_down_sync(0xffffffffu, ce, d);
        c  += __shfl_down_sync(0xffffffffu, c, d);
    }
    if ((threadIdx.x & 31) == 0 && c != 0.f) {
        atomicAdd(&g_loss_num, ce);
        atomicAdd(&g_loss_cnt, c);
    }
}

__global__ void finalize_kernel(float* __restrict__ out) {
    out[0] = g_loss_num / g_loss_cnt;
}

// ---------------- launch ---------------------------------------------------
extern "C" void kernel_launch(void* const* d_in, const int* in_sizes, int n_in,
                              void* d_out, int out_size) {
    const float*         x      = (const float*)d_in[0];
    const int*           ei     = (const int*)d_in[1];      // int32 (JAX x64 disabled)
    const int*           labels = (const int*)d_in[2];      // int32
    const unsigned char* mask   = (const unsigned char*)d_in[3];
    const float*         W1     = (const float*)d_in[4];
    const float*         a_src1 = (const float*)d_in[5];
    const float*         a_dst1 = (const float*)d_in[6];
    const float*         b1     = (const float*)d_in[7];
    const float*         W2     = (const float*)d_in[8];
    const float*         a_src2 = (const float*)d_in[9];
    const float*         a_dst2 = (const float*)d_in[10];
    const float*         b2     = (const float*)d_in[11];

    float* out  = (float*)d_out;
    float* emb1 = out + 1;
    float* emb2 = out + 1 + (size_t)NN * D1;

    // CSR build interleaved with gemm1 (gemm1 is CSR-independent; reorder
    // also shifts ncu's fixed capture slot onto a compute kernel).
    init_kernel<<<(NN + 255) / 256, 256>>>();
    count_kernel<<<(NE + 255) / 256, 256>>>(ei);
    scan_kernel<<<1, 1024>>>();
    gemm1_kernel<<<(NN + 63) / 64, 256>>>(x, W1);
    scatter_kernel<<<(NE + 255) / 256, 256>>>(ei);

    // layer 1
    alpha1_kernel<<<(NN * H1 + 255) / 256, 256>>>(a_src1, a_dst1);
    agg1_kernel<<<(NN * 32 + 255) / 256, 256>>>(emb1, b1);

    // layer 2
    gemm2_kernel<<<(NN + 63) / 64, 256>>>(W2);
    alpha2_kernel<<<(NN * H2 + 255) / 256, 256>>>(a_src2, a_dst2);
    agg2_kernel<<<(NN * 32 + 255) / 256, 256>>>(emb2, b2);

    // loss
    loss_kernel<<<(NN + 255) / 256, 256>>>(emb2, labels, mask);
    finalize_kernel<<<1, 1>>>(out);
}

// round 16
// speedup vs baseline: 1.1080x; 1.1080x over previous
#include <cuda_runtime.h>
#include <math.h>

#define NN 100000
#define NE 800000
#define KDIM 128
#define H1 8
#define C1 16
#define D1 128
#define H2 10
#define C2 10
#define D2 100
#define NEG_SLOPE 0.2f

// ---------------- scratch (device globals: no allocation allowed) ----------
__device__ float g_h1[NN * D1];      // x @ W1
__device__ float g_hact[NN * D1];    // elu(emb1)
__device__ float g_h2[NN * D2];      // hact @ W2
__device__ float g_as1[NN * H1];
__device__ float g_ad1[NN * H1];
__device__ float g_as2[NN * H2];
__device__ float g_ad2[NN * H2];
__device__ int   g_deg[NN];
__device__ int   g_off[NN + 1];
__device__ int   g_cur[NN];
__device__ int   g_src[NE];          // CSR-by-dst: source node per slot
__device__ float g_loss_num;
__device__ float g_loss_cnt;

// ---------------- CSR build ------------------------------------------------
__global__ void init_kernel() {
    int i = blockIdx.x * blockDim.x + threadIdx.x;
    if (i < NN) g_deg[i] = 0;
    if (i == 0) { g_loss_num = 0.f; g_loss_cnt = 0.f; }
}

__global__ void count_kernel(const int* __restrict__ ei) {
    int e = blockIdx.x * blockDim.x + threadIdx.x;
    if (e >= NE) return;
    int d = __ldg(&ei[NE + e]);
    if ((unsigned)d < NN) atomicAdd(&g_deg[d], 1);
}

__global__ void scan_kernel() {
    __shared__ int sh[1024];
    int t = threadIdx.x;
    const int CH = (NN + 1023) / 1024;   // 98
    int start = t * CH;
    int s = 0;
    for (int i = 0; i < CH; i++) {
        int idx = start + i;
        if (idx < NN) s += g_deg[idx];
    }
    sh[t] = s;
    __syncthreads();
    for (int d = 1; d < 1024; d <<= 1) {
        int v = (t >= d) ? sh[t - d] : 0;
        __syncthreads();
        sh[t] += v;
        __syncthreads();
    }
    int run = (t == 0) ? 0 : sh[t - 1];
    for (int i = 0; i < CH; i++) {
        int idx = start + i;
        if (idx < NN) { g_off[idx] = run; g_cur[idx] = run; run += g_deg[idx]; }
    }
    if (t == 1023) g_off[NN] = sh[1023];
}

__global__ void scatter_kernel(const int* __restrict__ ei) {
    int e = blockIdx.x * blockDim.x + threadIdx.x;
    if (e >= NE) return;
    int d = __ldg(&ei[NE + e]);
    int srcv = __ldg(&ei[e]);
    if ((unsigned)d >= NN || (unsigned)srcv >= NN) return;
    int pos = atomicAdd(&g_cur[d], 1);
    g_src[pos] = srcv;
}

// ---------------- SGEMM: Y[N, M] = X[N, 128] @ W[128, M] -------------------
// 256 threads/block, 64 rows x M cols per block.
// Thread owns cols {tx, tx+64} and 16 rows (R=16, C=2): per 4-k group
// 16 broadcast Xs LDS.128 + 2 Wt LDS.128 feed 128 FMAs (was 33:128).
// Wt stride 44 floats (176B = 11*16B, odd multiple) -> conflict-free LDS.128.
template <int M>
__device__ __forceinline__ void gemm_body(const float* __restrict__ X,
                                          const float* __restrict__ W,
                                          float* __restrict__ Y) {
    const int KC = 32;
    __shared__ float Wt[M][KC + 12];   // stride 44 floats: conflict-free
    __shared__ float Xs[64][KC];       // warp-uniform broadcast reads
    int t   = threadIdx.x;
    int tx  = t & 63;
    int ty  = t >> 6;                  // 0..3; uniform within a warp
    int rbase = ty * 16;
    int c0 = tx, c1 = tx + 64;
    int row0 = blockIdx.x * 64;
    float acc[32];                     // acc[r*2 + c], constant-indexed
#pragma unroll
    for (int r = 0; r < 32; r++) acc[r] = 0.f;

    for (int kc = 0; kc < KDIM; kc += KC) {
        for (int idx = t; idx < M * KC; idx += 256) {
            int m = idx % M, k = idx / M;           // coalesced over m
            Wt[m][k] = W[(size_t)(kc + k) * M + m];
        }
        for (int idx = t; idx < 64 * KC; idx += 256) {
            int r = idx / KC, k = idx % KC;
            int row = row0 + r;
            Xs[r][k] = (row < NN) ? X[(size_t)row * KDIM + kc + k] : 0.f;
        }
        __syncthreads();
#pragma unroll
        for (int kk = 0; kk < KC; kk += 4) {
            float4 w0 = *(const float4*)&Wt[c0][kk];
            float4 w1 = (c1 < M) ? *(const float4*)&Wt[c1][kk]
                                 : make_float4(0.f, 0.f, 0.f, 0.f);
#pragma unroll
            for (int r = 0; r < 16; r++) {
                float4 xv = *(const float4*)&Xs[rbase + r][kk];
                acc[r * 2 + 0] = fmaf(w0.x, xv.x, acc[r * 2 + 0]);
                acc[r * 2 + 0] = fmaf(w0.y, xv.y, acc[r * 2 + 0]);
                acc[r * 2 + 0] = fmaf(w0.z, xv.z, acc[r * 2 + 0]);
                acc[r * 2 + 0] = fmaf(w0.w, xv.w, acc[r * 2 + 0]);
                acc[r * 2 + 1] = fmaf(w1.x, xv.x, acc[r * 2 + 1]);
                acc[r * 2 + 1] = fmaf(w1.y, xv.y, acc[r * 2 + 1]);
                acc[r * 2 + 1] = fmaf(w1.z, xv.z, acc[r * 2 + 1]);
                acc[r * 2 + 1] = fmaf(w1.w, xv.w, acc[r * 2 + 1]);
            }
        }
        __syncthreads();
    }
#pragma unroll
    for (int r = 0; r < 16; r++) {
        int row = row0 + rbase + r;
        if (row < NN) {
            Y[(size_t)row * M + c0] = acc[r * 2 + 0];
            if (c1 < M) Y[(size_t)row * M + c1] = acc[r * 2 + 1];
        }
    }
}

__global__ void __launch_bounds__(256) gemm1_kernel(const float* __restrict__ X,
                                                    const float* __restrict__ W) {
    gemm_body<D1>(X, W, g_h1);
}
__global__ void __launch_bounds__(256) gemm2_kernel(const float* __restrict__ W) {
    gemm_body<D2>(g_hact, W, g_h2);
}

// ---------------- attention coefficients as/ad -----------------------------
template <int H, int C>
__device__ __forceinline__ void alpha_body(const float* __restrict__ Hm,
                                           const float* __restrict__ asr,
                                           const float* __restrict__ adt,
                                           float* __restrict__ o_as,
                                           float* __restrict__ o_ad) {
    int idx = blockIdx.x * blockDim.x + threadIdx.x;   // n*H + h
    if (idx >= NN * H) return;
    int n = idx / H, h = idx % H;
    const float* hp = Hm + (size_t)n * (H * C) + h * C;
    float s = 0.f, d = 0.f;
#pragma unroll
    for (int c = 0; c < C; c++) {
        float v = hp[c];
        s = fmaf(v, asr[h * C + c], s);
        d = fmaf(v, adt[h * C + c], d);
    }
    o_as[idx] = s;
    o_ad[idx] = d;
}

__global__ void alpha1_kernel(const float* __restrict__ asr, const float* __restrict__ adt) {
    alpha_body<H1, C1>(g_h1, asr, adt, g_as1, g_ad1);
}
__global__ void alpha2_kernel(const float* __restrict__ asr, const float* __restrict__ adt) {
    alpha_body<H2, C2>(g_h2, asr, adt, g_as2, g_ad2);
}

// ---------------- layer 1: single-pass flash-style softmax+agg -------------
// (R13-proven version: simple single-state online softmax.)
__global__ void agg1_kernel(float* __restrict__ emb1, const float* __restrict__ b1) {
    int warp = (blockIdx.x * blockDim.x + threadIdx.x) >> 5;
    int lane = threadIdx.x & 31;
    if (warp >= NN) return;
    int n = warp;
    int beg = g_off[n], end = g_off[n + 1];
    int h  = lane >> 2;
    int c0 = lane * 4;
    float adh = __ldg(&g_ad1[n * H1 + h]);

    float m = -3.0e38f, s = 0.f;
    float a0 = 0.f, a1 = 0.f, a2 = 0.f, a3 = 0.f;
    for (int e = beg; e < end; e++) {
        int src = __ldg(&g_src[e]);
        float l = __ldg(&g_as1[src * H1 + h]) + adh;
        l = l > 0.f ? l : NEG_SLOPE * l;
        float mn = fmaxf(m, l);
        float sc = __expf(m - mn);    // finite sentinel: never NaN
        float p  = __expf(l - mn);
        m = mn;
        s = fmaf(s, sc, p);
        float4 hv = __ldg((const float4*)&g_h1[(size_t)src * D1 + c0]);
        a0 = fmaf(a0, sc, p * hv.x);
        a1 = fmaf(a1, sc, p * hv.y);
        a2 = fmaf(a2, sc, p * hv.z);
        a3 = fmaf(a3, sc, p * hv.w);
    }
    float inv = 1.f / (s + 1e-16f);
    float v0 = a0 * inv + b1[c0 + 0];
    float v1 = a1 * inv + b1[c0 + 1];
    float v2 = a2 * inv + b1[c0 + 2];
    float v3 = a3 * inv + b1[c0 + 3];
    float* op = emb1 + (size_t)n * D1 + c0;
    op[0] = v0; op[1] = v1; op[2] = v2; op[3] = v3;
    float* hp = g_hact + (size_t)n * D1 + c0;
    hp[0] = v0 > 0.f ? v0 : expm1f(v0);
    hp[1] = v1 > 0.f ? v1 : expm1f(v1);
    hp[2] = v2 > 0.f ? v2 : expm1f(v2);
    hp[3] = v3 > 0.f ? v3 : expm1f(v3);
}

// ---------------- layer 2: softmax + aggregation + head-mean ---------------
__global__ void agg2_kernel(float* __restrict__ emb2, const float* __restrict__ b2) {
    __shared__ float sh[8][D2];
    int warp_l = threadIdx.x >> 5;
    int warp = (blockIdx.x * blockDim.x + threadIdx.x) >> 5;
    int lane = threadIdx.x & 31;
    if (warp >= NN) return;
    int n = warp;
    int beg = g_off[n], end = g_off[n + 1];

    int j = (lane < 30) ? (lane / 10) : 3;
    int h = (lane < 30) ? (lane % 10) : 0;
    float adh = __ldg(&g_ad2[n * H2 + h]);

    float m = -3.0e38f, s = 0.f;
    if (j < 3) {
        for (int e = beg + j; e < end; e += 3) {
            int src = __ldg(&g_src[e]);
            float l = __ldg(&g_as2[src * H2 + h]) + adh;
            l = l > 0.f ? l : NEG_SLOPE * l;
            float mn = fmaxf(m, l);
            s = s * __expf(m - mn) + __expf(l - mn);
            m = mn;
        }
    }
#pragma unroll
    for (int off = 10; off <= 20; off += 10) {
        float mo = __shfl_down_sync(0xffffffffu, m, off);
        float so = __shfl_down_sync(0xffffffffu, s, off);
        if (lane < 10) {
            float mn = fmaxf(m, mo);
            s = s * __expf(m - mn) + so * __expf(mo - mn);
            m = mn;
        }
    }
    float inv = 1.f / (s + 1e-16f);

    int cl = lane < 25 ? lane : 24;          // lanes 25..31 shadow lane 24 (writes guarded)
    int c0 = cl * 4;
    int hA = (c0 + 0) / C2, hB = (c0 + 1) / C2, hC = (c0 + 2) / C2, hD = (c0 + 3) / C2;
    float mA = __shfl_sync(0xffffffffu, m, hA),   iA = __shfl_sync(0xffffffffu, inv, hA);
    float mB = __shfl_sync(0xffffffffu, m, hB),   iB = __shfl_sync(0xffffffffu, inv, hB);
    float mC = __shfl_sync(0xffffffffu, m, hC),   iC = __shfl_sync(0xffffffffu, inv, hC);
    float mD = __shfl_sync(0xffffffffu, m, hD),   iD = __shfl_sync(0xffffffffu, inv, hD);
    float dA = __shfl_sync(0xffffffffu, adh, hA), dB = __shfl_sync(0xffffffffu, adh, hB);
    float dC = __shfl_sync(0xffffffffu, adh, hC), dD = __shfl_sync(0xffffffffu, adh, hD);

    float a0 = 0.f, a1 = 0.f, a2 = 0.f, a3 = 0.f;
    for (int e = beg; e < end; e++) {
        int src = __ldg(&g_src[e]);
        const float* hb = g_h2 + (size_t)src * D2;
        float4 hv = __ldg((const float4*)&hb[c0]);
        const float* ap = g_as2 + src * H2;
        float lA = __ldg(&ap[hA]) + dA; lA = lA > 0.f ? lA : NEG_SLOPE * lA;
        float lB = __ldg(&ap[hB]) + dB; lB = lB > 0.f ? lB : NEG_SLOPE * lB;
        float lC = __ldg(&ap[hC]) + dC; lC = lC > 0.f ? lC : NEG_SLOPE * lC;
        float lD = __ldg(&ap[hD]) + dD; lD = lD > 0.f ? lD : NEG_SLOPE * lD;
        a0 = fmaf(__expf(lA - mA) * iA, hv.x, a0);
        a1 = fmaf(__expf(lB - mB) * iB, hv.y, a1);
        a2 = fmaf(__expf(lC - mC) * iC, hv.z, a2);
        a3 = fmaf(__expf(lD - mD) * iD, hv.w, a3);
    }
    if (lane < 25) {
        sh[warp_l][c0 + 0] = a0;
        sh[warp_l][c0 + 1] = a1;
        sh[warp_l][c0 + 2] = a2;
        sh[warp_l][c0 + 3] = a3;
    }
    __syncwarp();
    if (lane < C2) {
        float acc = 0.f;
#pragma unroll
        for (int hh = 0; hh < H2; hh++) acc += sh[warp_l][hh * C2 + lane];
        emb2[(size_t)n * C2 + lane] = acc * (1.f / H2) + b2[lane];
    }
}

// ---------------- masked cross-entropy loss --------------------------------
__global__ void loss_kernel(const float* __restrict__ emb2,
                            const int* __restrict__ lab,
                            const unsigned char* __restrict__ mask) {
    int n = blockIdx.x * blockDim.x + threadIdx.x;
    float ce = 0.f, c = 0.f;
    if (n < NN && mask[n]) {
        const float* r = emb2 + (size_t)n * C2;
        float mx = r[0];
#pragma unroll
        for (int o = 1; o < C2; o++) mx = fmaxf(mx, r[o]);
        float se = 0.f;
#pragma unroll
        for (int o = 0; o < C2; o++) se += expf(r[o] - mx);
        float lse = mx + logf(se);
        int lb = lab[n];
        if ((unsigned)lb < C2) ce = lse - r[lb];
        c = 1.f;
    }
#pragma unroll
    for (int d = 16; d > 0; d >>= 1) {
        ce += __shfl_down_sync(0xffffffffu, ce, d);
        c  += __shfl_down_sync(0xffffffffu, c, d);
    }
    if ((threadIdx.x & 31) == 0 && c != 0.f) {
        atomicAdd(&g_loss_num, ce);
        atomicAdd(&g_loss_cnt, c);
    }
}

__global__ void finalize_kernel(float* __restrict__ out) {
    out[0] = g_loss_num / g_loss_cnt;
}

// ---------------- launch ---------------------------------------------------
extern "C" void kernel_launch(void* const* d_in, const int* in_sizes, int n_in,
                              void* d_out, int out_size) {
    const float*         x      = (const float*)d_in[0];
    const int*           ei     = (const int*)d_in[1];      // int32 (JAX x64 disabled)
    const int*           labels = (const int*)d_in[2];      // int32
    const unsigned char* mask   = (const unsigned char*)d_in[3];
    const float*         W1     = (const float*)d_in[4];
    const float*         a_src1 = (const float*)d_in[5];
    const float*         a_dst1 = (const float*)d_in[6];
    const float*         b1     = (const float*)d_in[7];
    const float*         W2     = (const float*)d_in[8];
    const float*         a_src2 = (const float*)d_in[9];
    const float*         a_dst2 = (const float*)d_in[10];
    const float*         b2     = (const float*)d_in[11];

    float* out  = (float*)d_out;
    float* emb1 = out + 1;
    float* emb2 = out + 1 + (size_t)NN * D1;

    // CSR build interleaved with gemm1 (gemm1 is CSR-independent; keeps the
    // ncu capture slot on gemm1).
    init_kernel<<<(NN + 255) / 256, 256>>>();
    count_kernel<<<(NE + 255) / 256, 256>>>(ei);
    scan_kernel<<<1, 1024>>>();
    gemm1_kernel<<<(NN + 63) / 64, 256>>>(x, W1);
    scatter_kernel<<<(NE + 255) / 256, 256>>>(ei);

    // layer 1
    alpha1_kernel<<<(NN * H1 + 255) / 256, 256>>>(a_src1, a_dst1);
    agg1_kernel<<<(NN * 32 + 255) / 256, 256>>>(emb1, b1);

    // layer 2
    gemm2_kernel<<<(NN + 63) / 64, 256>>>(W2);
    alpha2_kernel<<<(NN * H2 + 255) / 256, 256>>>(a_src2, a_dst2);
    agg2_kernel<<<(NN * 32 + 255) / 256, 256>>>(emb2, b2);

    // loss
    loss_kernel<<<(NN + 255) / 256, 256>>>(emb2, labels, mask);
    finalize_kernel<<<1, 1>>>(out);
}